// round 4
// baseline (speedup 1.0000x reference)
#include <cuda_runtime.h>
#include <math.h>

#define Bb 16
#define Gg 512
#define Pp 512
#define Ee 256
#define Hh 16
#define Kd 16
#define HK 256

typedef unsigned long long ull;

// Scratch (device globals: allocation-free rule)
__device__ float g_c1[Bb * HK];
__device__ float g_Kt[Bb * Hh * Pp * Kd];   // [B,H,P,Kd]
__device__ float g_Vt[Bb * Hh * Pp * Kd];
__device__ float g_Qt[Bb * Hh * Gg * Kd];
__device__ float g_attn[Bb * Gg * HK];
__device__ float g_mh[Bb * Gg * HK];
__device__ float g_s2[Bb * Gg * Pp];

// ---- packed f32x2 helpers ---------------------------------------------------
__device__ __forceinline__ ull dup2(float a) {
    ull r; asm("mov.b64 %0, {%1, %1};" : "=l"(r) : "f"(a)); return r;
}
__device__ __forceinline__ void fma2(ull& d, ull a, ull b) {
    asm("fma.rn.f32x2 %0, %1, %2, %3;" : "=l"(d) : "l"(a), "l"(b), "l"(d));
}
__device__ __forceinline__ float2 unpack2(ull v) {
    float2 f; asm("mov.b64 {%0, %1}, %2;" : "=f"(f.x), "=f"(f.y) : "l"(v)); return f;
}

// ---------------------------------------------------------------------------
__global__ void qbias_kernel(const float* __restrict__ input1,
                             const float* __restrict__ Wq) {
    int b = blockIdx.x;
    int n = threadIdx.x;
    const float* x = input1 + b * Ee;
    float acc = 0.f;
#pragma unroll 4
    for (int e = 0; e < Ee; e++) acc += x[e] * Wq[e * HK + n];
    g_c1[b * HK + n] = acc;
}

// ---------------------------------------------------------------------------
// 64x128 tile GEMM (256 threads, 4x8 micro-tile packed f32x2, BK=8)
// ---------------------------------------------------------------------------
#define GEMM_PROLOG()                                                     \
    __shared__ float As[8][68];                                           \
    __shared__ float Bs[8][132];                                          \
    const int tid = threadIdx.x;                                          \
    const int tm = tid >> 4, tn = tid & 15;                               \
    const int ar = tid >> 1, ac = (tid & 1) * 4;                          \
    const int br = tid >> 5, bc = (tid & 31) * 4;                         \
    ull acc2[4][4];                                                       \
    _Pragma("unroll") for (int i = 0; i < 4; i++)                         \
    _Pragma("unroll") for (int j = 0; j < 4; j++) acc2[i][j] = 0ull;

#define GEMM_INNER2()                                                     \
    _Pragma("unroll")                                                     \
    for (int kk = 0; kk < 8; kk++) {                                      \
        float4 a = *(const float4*)&As[kk][tm * 4];                       \
        const ull* bp = (const ull*)&Bs[kk][tn * 8];                      \
        ull b0 = bp[0], b1 = bp[1], b2 = bp[2], b3 = bp[3];               \
        ull d0 = dup2(a.x), d1 = dup2(a.y), d2 = dup2(a.z), d3 = dup2(a.w); \
        fma2(acc2[0][0], d0, b0); fma2(acc2[0][1], d0, b1);               \
        fma2(acc2[0][2], d0, b2); fma2(acc2[0][3], d0, b3);               \
        fma2(acc2[1][0], d1, b0); fma2(acc2[1][1], d1, b1);               \
        fma2(acc2[1][2], d1, b2); fma2(acc2[1][3], d1, b3);               \
        fma2(acc2[2][0], d2, b0); fma2(acc2[2][1], d2, b1);               \
        fma2(acc2[2][2], d2, b2); fma2(acc2[2][3], d2, b3);               \
        fma2(acc2[3][0], d3, b0); fma2(acc2[3][1], d3, b1);               \
        fma2(acc2[3][2], d3, b2); fma2(acc2[3][3], d3, b3);               \
    }

// NN mainloop, A tile staged by threads 0-127 (transposed), B by all 256
#define GEMM_LOOP_NN(Aptr, Wptr, m0, n0)                                  \
    {                                                                     \
        const float* Ag = (Aptr) + (size_t)((m0) + ar) * 256 + ac;        \
        const float* Bg = (Wptr) + (size_t)br * 256 + (n0) + bc;          \
        float4 av = make_float4(0.f, 0.f, 0.f, 0.f), bv;                  \
        if (tid < 128) av = *(const float4*)Ag;                           \
        bv = *(const float4*)Bg;                                          \
        for (int k0 = 0; k0 < 256; k0 += 8) {                             \
            if (tid < 128) {                                              \
                As[ac + 0][ar] = av.x; As[ac + 1][ar] = av.y;             \
                As[ac + 2][ar] = av.z; As[ac + 3][ar] = av.w;             \
            }                                                             \
            *(float4*)&Bs[br][bc] = bv;                                   \
            __syncthreads();                                              \
            if (k0 < 248) {                                               \
                if (tid < 128) av = *(const float4*)(Ag + k0 + 8);        \
                bv = *(const float4*)(Bg + (size_t)(k0 + 8) * 256);       \
            }                                                             \
            GEMM_INNER2();                                                \
            __syncthreads();                                              \
        }                                                                 \
    }

// NT mainloop: B operand also [row][k] row-major; both staged transposed
#define GEMM_LOOP_NT(Aptr, Bptr, m0, n0)                                  \
    {                                                                     \
        const int brr = tid >> 1, bcc = (tid & 1) * 4;                    \
        const float* Ag = (Aptr) + (size_t)((m0) + ar) * 256 + ac;        \
        const float* Bg = (Bptr) + (size_t)((n0) + brr) * 256 + bcc;      \
        float4 av = make_float4(0.f, 0.f, 0.f, 0.f), bv;                  \
        if (tid < 128) av = *(const float4*)Ag;                           \
        bv = *(const float4*)Bg;                                          \
        for (int k0 = 0; k0 < 256; k0 += 8) {                             \
            if (tid < 128) {                                              \
                As[ac + 0][ar] = av.x; As[ac + 1][ar] = av.y;             \
                As[ac + 2][ar] = av.z; As[ac + 3][ar] = av.w;             \
            }                                                             \
            Bs[bcc + 0][brr] = bv.x; Bs[bcc + 1][brr] = bv.y;             \
            Bs[bcc + 2][brr] = bv.z; Bs[bcc + 3][brr] = bv.w;             \
            __syncthreads();                                              \
            if (k0 < 248) {                                               \
                if (tid < 128) av = *(const float4*)(Ag + k0 + 8);        \
                bv = *(const float4*)(Bg + k0 + 8);                       \
            }                                                             \
            GEMM_INNER2();                                                \
            __syncthreads();                                              \
        }                                                                 \
    }

// ---------------------------------------------------------------------------
// Fused projections: z=0 K, z=1 V, z=2 Q (+c1 + t*wq_last). Heads layout out.
// ---------------------------------------------------------------------------
__global__ __launch_bounds__(256, 3)
void proj_kernel(const float* __restrict__ enc, const float* __restrict__ inp2,
                 const float* __restrict__ Wk, const float* __restrict__ Wv,
                 const float* __restrict__ Wqm, const float* __restrict__ tvec,
                 const float* __restrict__ wql) {
    const int z = blockIdx.z;
    const float* A = (z == 2) ? inp2 : enc;
    const float* W = (z == 0) ? Wk : (z == 1) ? Wv : Wqm;
    float* C = (z == 0) ? g_Kt : (z == 1) ? g_Vt : g_Qt;
    const int m0 = blockIdx.x * 64, n0 = blockIdx.y * 128;

    GEMM_PROLOG();
    GEMM_LOOP_NN(A, W, m0, n0);

#pragma unroll
    for (int i = 0; i < 4; i++) {
        int m = m0 + tm * 4 + i;
        int bb = m >> 9, r = m & 511;
        int nb = n0 + tn * 8;
        float v[8];
#pragma unroll
        for (int j = 0; j < 4; j++) {
            float2 f = unpack2(acc2[i][j]);
            v[2 * j] = f.x; v[2 * j + 1] = f.y;
        }
        if (z == 2) {
            float t = tvec[m];
#pragma unroll
            for (int j = 0; j < 8; j++) {
                int n = nb + j;
                v[j] += g_c1[bb * HK + n] + t * wql[n];
            }
        }
        int h = nb >> 4, kcb = nb & 15;
        float* dst = C + (((size_t)(bb * Hh + h) * 512 + r) << 4) + kcb;
        *(float4*)dst = make_float4(v[0], v[1], v[2], v[3]);
        *(float4*)(dst + 4) = make_float4(v[4], v[5], v[6], v[7]);
    }
}

// ---------------------------------------------------------------------------
__global__ __launch_bounds__(256, 3)
void wc_kernel(const float* __restrict__ Wcw, const float* __restrict__ bias) {
    const int m0 = blockIdx.x * 64, n0 = blockIdx.y * 128;
    GEMM_PROLOG();
    GEMM_LOOP_NN(g_attn, Wcw, m0, n0);

#pragma unroll
    for (int i = 0; i < 4; i++) {
        int m = m0 + tm * 4 + i;
        int nb = n0 + tn * 8;
        float v[8];
#pragma unroll
        for (int j = 0; j < 4; j++) {
            float2 f = unpack2(acc2[i][j]);
            v[2 * j] = f.x + bias[nb + 2 * j];
            v[2 * j + 1] = f.y + bias[nb + 2 * j + 1];
        }
        float* dst = g_mh + (size_t)m * 256 + nb;
        *(float4*)dst = make_float4(v[0], v[1], v[2], v[3]);
        *(float4*)(dst + 4) = make_float4(v[4], v[5], v[6], v[7]);
    }
}

// ---------------------------------------------------------------------------
__device__ __forceinline__ float fast_tanh10(float x) {
    x = fminf(fmaxf(x, -15.f), 15.f);
    float e = __expf(2.f * x);
    return 10.f * (1.f - __fdividef(2.f, e + 1.f));
}

__global__ __launch_bounds__(256, 3)
void pointer_gemm(const float* __restrict__ enc, const float* __restrict__ mask) {
    const int b = blockIdx.z;
    const int g0 = blockIdx.x * 64, p0 = blockIdx.y * 128;
    const float* A = g_mh + (size_t)b * Gg * HK;
    const float* Bm = enc + (size_t)b * Pp * Ee;

    GEMM_PROLOG();
    GEMM_LOOP_NT(A, Bm, g0, p0);

#pragma unroll
    for (int i = 0; i < 4; i++) {
        int g = g0 + tm * 4 + i;
        size_t base = (size_t)(b * Gg + g) * Pp + p0 + tn * 8;
        float v[8];
#pragma unroll
        for (int j = 0; j < 4; j++) {
            float2 f = unpack2(acc2[i][j]);
            v[2 * j] = fast_tanh10(f.x * 0.0625f) + mask[base + 2 * j];
            v[2 * j + 1] = fast_tanh10(f.y * 0.0625f) + mask[base + 2 * j + 1];
        }
        *(float4*)&g_s2[base] = make_float4(v[0], v[1], v[2], v[3]);
        *(float4*)&g_s2[base + 4] = make_float4(v[4], v[5], v[6], v[7]);
    }
}

// ---------------------------------------------------------------------------
// Attention. Block = (g-half, h, b): 256 queries, 8 per pass.
// Scores stay in registers through a shfl softmax; only exp stored (sS[p][8]).
// O-phase packed over q-pairs with fma2.
// ---------------------------------------------------------------------------
#define ATTN_SMEM_FLOATS (8192 + 6144 + 8448 + 128 + 64 + 64)
#define ATTN_SMEM_BYTES (ATTN_SMEM_FLOATS * 4)

__global__ __launch_bounds__(256, 2)
void attn_kernel(const float* __restrict__ mask) {
    extern __shared__ float sm[];
    float* sV = sm;                  // [512][16]
    float* sS = sV + 8192;           // [512][12] (8 used) exp scores
    float* sO = sS + 6144;           // [64][132] : [pg][kcg*8+q]
    float* sq = sO + 8448;           // [8][16]
    float* swm1 = sq + 128;          // [8 warp][8 q] maxes
    float* swm2 = swm1 + 64;         // [8 warp][8 q] sums

    const int tid = threadIdx.x;
    const int gbase = blockIdx.x * 256;
    const int h = blockIdx.y, b = blockIdx.z;
    const float* Kb = g_Kt + (size_t)(b * Hh + h) * Pp * Kd;
    const float* Vb = g_Vt + (size_t)(b * Hh + h) * Pp * Kd;
    const float* Qb = g_Qt + (size_t)(b * Hh + h) * Gg * Kd;

    // Stage V (natural stride 16)
    for (int i = tid; i < 2048; i += 256)
        ((float4*)sV)[i] = ((const float4*)Vb)[i];

    // This thread's two K columns -> packed register pairs
    ull k0p[8], k1p[8];
    {
        const ulonglong2* K0 = (const ulonglong2*)(Kb + tid * 16);
        const ulonglong2* K1 = (const ulonglong2*)(Kb + (tid + 256) * 16);
#pragma unroll
        for (int j = 0; j < 4; j++) {
            ulonglong2 u = K0[j]; k0p[2 * j] = u.x; k0p[2 * j + 1] = u.y;
            ulonglong2 w = K1[j]; k1p[2 * j] = w.x; k1p[2 * j + 1] = w.y;
        }
    }
    __syncthreads();

    const int warp = tid >> 5, lane = tid & 31;
    const int kcq = tid & 3, pg = tid >> 2;   // O-phase map

    for (int pass = 0; pass < 32; pass++) {
        const int g0q = gbase + pass * 8;

        if (tid < 128) sq[tid] = Qb[(g0q + (tid >> 4)) * 16 + (tid & 15)];

        // prefetch mask (coalesced; consumed after the dot products)
        float mk0[8], mk1[8];
        const float* mbase = mask + (size_t)(b * Gg + g0q) * Pp;
#pragma unroll
        for (int q = 0; q < 8; q++) {
            mk0[q] = mbase[q * Pp + tid];
            mk1[q] = mbase[q * Pp + tid + 256];
        }
        __syncthreads();   // A

        // scores in registers (this thread's p = tid and tid+256)
        float s0[8], s1[8];
#pragma unroll
        for (int q = 0; q < 8; q++) {
            const ull* q2 = (const ull*)&sq[q * 16];
            ull a0 = 0ull, a1 = 0ull;
#pragma unroll
            for (int j = 0; j < 8; j++) {
                ull qj = q2[j];
                fma2(a0, qj, k0p[j]);
                fma2(a1, qj, k1p[j]);
            }
            float2 f0 = unpack2(a0), f1 = unpack2(a1);
            s0[q] = (f0.x + f0.y) * 0.25f + mk0[q];
            s1[q] = (f1.x + f1.y) * 0.25f + mk1[q];
        }

        // register/shfl max
        float mx[8];
#pragma unroll
        for (int q = 0; q < 8; q++) {
            float m = fmaxf(s0[q], s1[q]);
#pragma unroll
            for (int o = 16; o > 0; o >>= 1)
                m = fmaxf(m, __shfl_xor_sync(0xffffffffu, m, o));
            mx[q] = m;
        }
        if (lane == 0) {
#pragma unroll
            for (int q = 0; q < 8; q++) swm1[warp * 8 + q] = mx[q];
        }
        __syncthreads();   // B

        float M[8];
#pragma unroll
        for (int q = 0; q < 8; q++) {
            float m = swm1[q];
#pragma unroll
            for (int w = 1; w < 8; w++) m = fmaxf(m, swm1[w * 8 + q]);
            M[q] = m;
        }

        // exp + shfl sum; write exp to sS[p][q] (packed rows of 8)
        float e0[8], e1[8];
#pragma unroll
        for (int q = 0; q < 8; q++) {
            e0[q] = __expf(s0[q] - M[q]);
            e1[q] = __expf(s1[q] - M[q]);
            float s = e0[q] + e1[q];
#pragma unroll
            for (int o = 16; o > 0; o >>= 1)
                s += __shfl_xor_sync(0xffffffffu, s, o);
            if (lane == 0) swm2[warp * 8 + q] = s;
        }
        {
            float* d0 = &sS[tid * 12];
            *(float4*)d0 = make_float4(e0[0], e0[1], e0[2], e0[3]);
            *(float4*)(d0 + 4) = make_float4(e0[4], e0[5], e0[6], e0[7]);
            float* d1 = &sS[(tid + 256) * 12];
            *(float4*)d1 = make_float4(e1[0], e1[1], e1[2], e1[3]);
            *(float4*)(d1 + 4) = make_float4(e1[4], e1[5], e1[6], e1[7]);
        }
        __syncthreads();   // C

        // O phase: thread (kcq, pg): p = pg + 64*i, 8 iters
        // acc oa[kc 0..3][qpair 0..3] packed over q
        {
            ull oa[4][4];
#pragma unroll
            for (int c = 0; c < 4; c++)
#pragma unroll
                for (int j = 0; j < 4; j++) oa[c][j] = 0ull;

#pragma unroll
            for (int i2 = 0; i2 < 8; i2++) {
                int p = pg + (i2 << 6);
                float4 v4 = *(const float4*)&sV[p * 16 + kcq * 4];
                const ull* sp = (const ull*)&sS[p * 12];
                ull sp0 = sp[0], sp1 = sp[1], sp2 = sp[2], sp3 = sp[3];
                ull dv0 = dup2(v4.x), dv1 = dup2(v4.y),
                    dv2 = dup2(v4.z), dv3 = dup2(v4.w);
                fma2(oa[0][0], sp0, dv0); fma2(oa[0][1], sp1, dv0);
                fma2(oa[0][2], sp2, dv0); fma2(oa[0][3], sp3, dv0);
                fma2(oa[1][0], sp0, dv1); fma2(oa[1][1], sp1, dv1);
                fma2(oa[1][2], sp2, dv1); fma2(oa[1][3], sp3, dv1);
                fma2(oa[2][0], sp0, dv2); fma2(oa[2][1], sp1, dv2);
                fma2(oa[2][2], sp2, dv2); fma2(oa[2][3], sp3, dv2);
                fma2(oa[3][0], sp0, dv3); fma2(oa[3][1], sp1, dv3);
                fma2(oa[3][2], sp2, dv3); fma2(oa[3][3], sp3, dv3);
            }
            // store partials: sO[pg*132 + (kcq*4+c)*8 + 2*j]
            float* base = &sO[pg * 132 + kcq * 32];
#pragma unroll
            for (int c = 0; c < 4; c++)
#pragma unroll
                for (int j = 0; j < 4; j++)
                    *(ull*)(base + c * 8 + 2 * j) = oa[c][j];
        }
        __syncthreads();   // D

        // reduce 64 partials; tid<128: q = tid&7, kcg = tid>>3
        if (tid < 128) {
            int q = tid & 7, kcg = tid >> 3;
            float ssum = swm2[q];
#pragma unroll
            for (int w = 1; w < 8; w++) ssum += swm2[w * 8 + q];
            float inv = __fdividef(1.f, ssum);
            float a0 = 0.f, a1 = 0.f, a2 = 0.f, a3 = 0.f;
#pragma unroll
            for (int pgi = 0; pgi < 64; pgi += 4) {
                a0 += sO[(pgi + 0) * 132 + tid];
                a1 += sO[(pgi + 1) * 132 + tid];
                a2 += sO[(pgi + 2) * 132 + tid];
                a3 += sO[(pgi + 3) * 132 + tid];
            }
            g_attn[(size_t)(b * Gg + g0q + q) * HK + h * Kd + kcg] =
                (a0 + a1 + a2 + a3) * inv;
        }
    }
}

// ---------------------------------------------------------------------------
__global__ __launch_bounds__(256)
void softmax_kernel(float* __restrict__ out) {
    __shared__ float sred[8];
    __shared__ float sbc[2];
    const int row = blockIdx.x;
    const int tid = threadIdx.x;
    const float* in = g_s2 + (size_t)row * Pp;

    float v0 = in[tid], v1 = in[tid + 256];
    float lmax = fmaxf(v0, v1);
#pragma unroll
    for (int o = 16; o > 0; o >>= 1)
        lmax = fmaxf(lmax, __shfl_xor_sync(0xffffffffu, lmax, o));
    if ((tid & 31) == 0) sred[tid >> 5] = lmax;
    __syncthreads();
    if (tid == 0) {
        float m = sred[0];
#pragma unroll
        for (int w = 1; w < 8; w++) m = fmaxf(m, sred[w]);
        sbc[0] = m;
    }
    __syncthreads();
    float smax = sbc[0];

    float e0 = __expf(v0 - smax), e1 = __expf(v1 - smax);
    float lsum = e0 + e1;
#pragma unroll
    for (int o = 16; o > 0; o >>= 1)
        lsum += __shfl_xor_sync(0xffffffffu, lsum, o);
    if ((tid & 31) == 0) sred[tid >> 5] = lsum;
    __syncthreads();
    if (tid == 0) {
        float s = 0.f;
#pragma unroll
        for (int w = 0; w < 8; w++) s += sred[w];
        sbc[1] = 1.f / s;
    }
    __syncthreads();
    float inv = sbc[1];
    out[(size_t)row * Pp + tid] = e0 * inv;
    out[(size_t)row * Pp + tid + 256] = e1 * inv;
}

// ---------------------------------------------------------------------------
extern "C" void kernel_launch(void* const* d_in, const int* in_sizes, int n_in,
                              void* d_out, int out_size) {
    const float* input1 = (const float*)d_in[0];
    const float* input2 = (const float*)d_in[1];
    const float* ctime  = (const float*)d_in[2];
    const float* mask   = (const float*)d_in[3];
    const float* enc    = (const float*)d_in[4];
    const float* Wq     = (const float*)d_in[5];
    const float* Wk     = (const float*)d_in[6];
    const float* Wv     = (const float*)d_in[7];
    const float* Wcw    = (const float*)d_in[8];
    const float* Wcb    = (const float*)d_in[9];
    float* out = (float*)d_out;

    qbias_kernel<<<Bb, 256>>>(input1, Wq);

    proj_kernel<<<dim3(128, 2, 3), 256>>>(enc, input2, Wk, Wv,
                                          Wq + Ee * HK, ctime, Wq + 2 * Ee * HK);

    cudaFuncSetAttribute(attn_kernel, cudaFuncAttributeMaxDynamicSharedMemorySize,
                         ATTN_SMEM_BYTES);
    attn_kernel<<<dim3(2, Hh, Bb), 256, ATTN_SMEM_BYTES>>>(mask);

    wc_kernel<<<dim3(128, 2), 256>>>(Wcw, Wcb);

    pointer_gemm<<<dim3(8, 4, Bb), 256>>>(enc, mask);

    softmax_kernel<<<Bb * Gg, 256>>>(out);
}

// round 5
// speedup vs baseline: 1.1854x; 1.1854x over previous
#include <cuda_runtime.h>
#include <math.h>

#define Bb 16
#define Gg 512
#define Pp 512
#define Ee 256
#define Hh 16
#define Kd 16
#define HK 256

typedef unsigned long long ull;

// Scratch (device globals: allocation-free rule)
__device__ float g_c1[Bb * HK];
__device__ float g_Kt[Bb * Hh * Pp * Kd];   // [B,H,P,Kd]
__device__ float g_Vt[Bb * Hh * Pp * Kd];
__device__ float g_Qt[Bb * Hh * Gg * Kd];
__device__ float g_attn[Bb * Gg * HK];
__device__ float g_mh[Bb * Gg * HK];
__device__ float g_s2[Bb * Gg * Pp];

// ---- packed f32x2 helpers ---------------------------------------------------
__device__ __forceinline__ ull dup2(float a) {
    ull r; asm("mov.b64 %0, {%1, %1};" : "=l"(r) : "f"(a)); return r;
}
__device__ __forceinline__ void fma2(ull& d, ull a, ull b) {
    asm("fma.rn.f32x2 %0, %1, %2, %3;" : "=l"(d) : "l"(a), "l"(b), "l"(d));
}
__device__ __forceinline__ float2 unpack2(ull v) {
    float2 f; asm("mov.b64 {%0, %1}, %2;" : "=f"(f.x), "=f"(f.y) : "l"(v)); return f;
}
__device__ __forceinline__ ull add2(ull a, ull b) {
    ull r; asm("add.rn.f32x2 %0, %1, %2;" : "=l"(r) : "l"(a), "l"(b)); return r;
}
__device__ __forceinline__ ull mul2(ull a, ull b) {
    ull r; asm("mul.rn.f32x2 %0, %1, %2;" : "=l"(r) : "l"(a), "l"(b)); return r;
}

union F4U { float4 f; ull u[2]; };

// ---------------------------------------------------------------------------
__global__ void qbias_kernel(const float* __restrict__ input1,
                             const float* __restrict__ Wq) {
    int b = blockIdx.x;
    int n = threadIdx.x;
    const float* x = input1 + b * Ee;
    float acc = 0.f;
#pragma unroll 4
    for (int e = 0; e < Ee; e++) acc += x[e] * Wq[e * HK + n];
    g_c1[b * HK + n] = acc;
}

// ---------------------------------------------------------------------------
// 128x128 tile GEMM (256 threads, 8x8 micro-tile via 8x4 packed f32x2, BK=8)
// (round-3 proven version)
// ---------------------------------------------------------------------------
#define GEMM_PROLOG()                                                     \
    __shared__ float As[8][132];                                          \
    __shared__ float Bs[8][132];                                          \
    const int tid = threadIdx.x;                                          \
    const int warp = tid >> 5, lane = tid & 31;                           \
    const int tm = ((warp >> 2) << 3) + (lane >> 2);                      \
    const int tn = ((warp & 3) << 2) + (lane & 3);                        \
    const int ar = tid >> 1, ac = (tid & 1) * 4;                          \
    const int br = tid >> 5, bc = (tid & 31) * 4;                         \
    ull acc2[8][4];                                                       \
    _Pragma("unroll") for (int i = 0; i < 8; i++)                         \
    _Pragma("unroll") for (int j = 0; j < 4; j++) acc2[i][j] = 0ull;

#define GEMM_INNER2()                                                     \
    _Pragma("unroll")                                                     \
    for (int kk = 0; kk < 8; kk++) {                                      \
        float4 a0 = *(const float4*)&As[kk][tm * 8];                      \
        float4 a1 = *(const float4*)&As[kk][tm * 8 + 4];                  \
        const ull* bp = (const ull*)&Bs[kk][tn * 8];                      \
        ull b0 = bp[0], b1 = bp[1], b2 = bp[2], b3 = bp[3];               \
        float aa[8] = {a0.x, a0.y, a0.z, a0.w, a1.x, a1.y, a1.z, a1.w};   \
        _Pragma("unroll") for (int i = 0; i < 8; i++) {                   \
            ull ad = dup2(aa[i]);                                         \
            fma2(acc2[i][0], ad, b0);                                     \
            fma2(acc2[i][1], ad, b1);                                     \
            fma2(acc2[i][2], ad, b2);                                     \
            fma2(acc2[i][3], ad, b3);                                     \
        }                                                                 \
    }

#define GEMM_LOOP_NN(Aptr, Wptr, m0, n0)                                  \
    {                                                                     \
        const float* Ag = (Aptr) + (size_t)((m0) + ar) * 256 + ac;        \
        const float* Bg = (Wptr) + (size_t)br * 256 + (n0) + bc;          \
        float4 av = *(const float4*)Ag;                                   \
        float4 bv = *(const float4*)Bg;                                   \
        for (int k0 = 0; k0 < 256; k0 += 8) {                             \
            As[ac + 0][ar] = av.x; As[ac + 1][ar] = av.y;                 \
            As[ac + 2][ar] = av.z; As[ac + 3][ar] = av.w;                 \
            *(float4*)&Bs[br][bc] = bv;                                   \
            __syncthreads();                                              \
            if (k0 < 248) {                                               \
                av = *(const float4*)(Ag + k0 + 8);                       \
                bv = *(const float4*)(Bg + (size_t)(k0 + 8) * 256);       \
            }                                                             \
            GEMM_INNER2();                                                \
            __syncthreads();                                              \
        }                                                                 \
    }

#define GEMM_LOOP_NT(Aptr, Bptr, m0, n0)                                  \
    {                                                                     \
        const float* Ag = (Aptr) + (size_t)((m0) + ar) * 256 + ac;        \
        const float* Bg2 = (Bptr) + (size_t)((n0) + ar) * 256 + ac;       \
        float4 av = *(const float4*)Ag;                                   \
        float4 bv = *(const float4*)Bg2;                                  \
        for (int k0 = 0; k0 < 256; k0 += 8) {                             \
            As[ac + 0][ar] = av.x; As[ac + 1][ar] = av.y;                 \
            As[ac + 2][ar] = av.z; As[ac + 3][ar] = av.w;                 \
            Bs[ac + 0][ar] = bv.x; Bs[ac + 1][ar] = bv.y;                 \
            Bs[ac + 2][ar] = bv.z; Bs[ac + 3][ar] = bv.w;                 \
            __syncthreads();                                              \
            if (k0 < 248) {                                               \
                av = *(const float4*)(Ag + k0 + 8);                       \
                bv = *(const float4*)(Bg2 + k0 + 8);                      \
            }                                                             \
            GEMM_INNER2();                                                \
            __syncthreads();                                              \
        }                                                                 \
    }

// ---------------------------------------------------------------------------
// Fused projections: z=0 K, z=1 V, z=2 Q (+c1 + t*wq_last). Heads layout out.
// ---------------------------------------------------------------------------
__global__ __launch_bounds__(256, 2)
void proj_kernel(const float* __restrict__ enc, const float* __restrict__ inp2,
                 const float* __restrict__ Wk, const float* __restrict__ Wv,
                 const float* __restrict__ Wqm, const float* __restrict__ tvec,
                 const float* __restrict__ wql) {
    const int z = blockIdx.z;
    const float* A = (z == 2) ? inp2 : enc;
    const float* W = (z == 0) ? Wk : (z == 1) ? Wv : Wqm;
    float* C = (z == 0) ? g_Kt : (z == 1) ? g_Vt : g_Qt;
    const int m0 = blockIdx.x * 128, n0 = blockIdx.y * 128;

    GEMM_PROLOG();
    GEMM_LOOP_NN(A, W, m0, n0);

#pragma unroll
    for (int i = 0; i < 8; i++) {
        int m = m0 + tm * 8 + i;
        int bb = m >> 9, r = m & 511;
        int nb = n0 + tn * 8;
        float v[8];
#pragma unroll
        for (int j = 0; j < 4; j++) {
            float2 f = unpack2(acc2[i][j]);
            v[2 * j] = f.x; v[2 * j + 1] = f.y;
        }
        if (z == 2) {
            float t = tvec[m];
#pragma unroll
            for (int j = 0; j < 8; j++) {
                int n = nb + j;
                v[j] += g_c1[bb * HK + n] + t * wql[n];
            }
        }
        int h = nb >> 4, kcb = nb & 15;
        float* dst = C + (((size_t)(bb * Hh + h) * 512 + r) << 4) + kcb;
        *(float4*)dst = make_float4(v[0], v[1], v[2], v[3]);
        *(float4*)(dst + 4) = make_float4(v[4], v[5], v[6], v[7]);
    }
}

// ---------------------------------------------------------------------------
__global__ __launch_bounds__(256, 2)
void wc_kernel(const float* __restrict__ Wcw, const float* __restrict__ bias) {
    const int m0 = blockIdx.x * 128, n0 = blockIdx.y * 128;
    GEMM_PROLOG();
    GEMM_LOOP_NN(g_attn, Wcw, m0, n0);

#pragma unroll
    for (int i = 0; i < 8; i++) {
        int m = m0 + tm * 8 + i;
        int nb = n0 + tn * 8;
        float v[8];
#pragma unroll
        for (int j = 0; j < 4; j++) {
            float2 f = unpack2(acc2[i][j]);
            v[2 * j] = f.x + bias[nb + 2 * j];
            v[2 * j + 1] = f.y + bias[nb + 2 * j + 1];
        }
        float* dst = g_mh + (size_t)m * 256 + nb;
        *(float4*)dst = make_float4(v[0], v[1], v[2], v[3]);
        *(float4*)(dst + 4) = make_float4(v[4], v[5], v[6], v[7]);
    }
}

// ---------------------------------------------------------------------------
__device__ __forceinline__ float fast_tanh10(float x) {
    x = fminf(fmaxf(x, -15.f), 15.f);
    float e = __expf(2.f * x);
    return 10.f * (1.f - __fdividef(2.f, e + 1.f));
}

__global__ __launch_bounds__(256, 2)
void pointer_gemm(const float* __restrict__ enc, const float* __restrict__ mask) {
    const int b = blockIdx.z;
    const int g0 = blockIdx.x * 128, p0 = blockIdx.y * 128;
    const float* A = g_mh + (size_t)b * Gg * HK;
    const float* Bm = enc + (size_t)b * Pp * Ee;

    GEMM_PROLOG();
    GEMM_LOOP_NT(A, Bm, g0, p0);

#pragma unroll
    for (int i = 0; i < 8; i++) {
        int g = g0 + tm * 8 + i;
        size_t base = (size_t)(b * Gg + g) * Pp + p0 + tn * 8;
        float v[8];
#pragma unroll
        for (int j = 0; j < 4; j++) {
            float2 f = unpack2(acc2[i][j]);
            v[2 * j] = fast_tanh10(f.x * 0.0625f) + mask[base + 2 * j];
            v[2 * j + 1] = fast_tanh10(f.y * 0.0625f) + mask[base + 2 * j + 1];
        }
        *(float4*)&g_s2[base] = make_float4(v[0], v[1], v[2], v[3]);
        *(float4*)&g_s2[base + 4] = make_float4(v[4], v[5], v[6], v[7]);
    }
}

// ---------------------------------------------------------------------------
// Warp-autonomous attention. Block = (g-half, h, b), 8 warps, 32 q per warp.
// K+V staged once (stride-20 rows: conflict-free, 16B-aligned). ONE barrier.
// Per query: score via fma2 from sK, warp shfl softmax, AV via fma2 from sV,
// reduce-scatter butterfly lands kc on its writer lane.
// ---------------------------------------------------------------------------
#define AT_STR 20
#define ATTN_SMEM_BYTES (2 * 512 * AT_STR * 4)   // 81920 B

__global__ __launch_bounds__(256, 2)
void attn_kernel(const float* __restrict__ mask) {
    extern __shared__ float sm[];
    float* sK = sm;                   // [512][20]
    float* sV = sm + 512 * AT_STR;    // [512][20]

    const int tid = threadIdx.x;
    const int gbase = blockIdx.x * 256;
    const int h = blockIdx.y, b = blockIdx.z;
    const float* Kb = g_Kt + (size_t)(b * Hh + h) * Pp * Kd;
    const float* Vb = g_Vt + (size_t)(b * Hh + h) * Pp * Kd;
    const float* Qb = g_Qt + (size_t)(b * Hh + h) * Gg * Kd;

    // Stage K and V (stride 20 words = 80 B rows)
    for (int i = tid; i < 2048; i += 256) {
        int p = i >> 2, c = (i & 3) * 4;
        *(float4*)&sK[p * AT_STR + c] = ((const float4*)Kb)[i];
        *(float4*)&sV[p * AT_STR + c] = ((const float4*)Vb)[i];
    }
    __syncthreads();   // the ONLY block barrier

    const int warp = tid >> 5, lane = tid & 31;
    // kc this lane will write after the reduce-scatter
    const int kcout = (((lane >> 4) & 1) << 3) | (((lane >> 3) & 1) << 2) |
                      (((lane >> 2) & 1) << 1) | ((lane >> 1) & 1);

    for (int qi = 0; qi < 32; qi++) {
        const int g = gbase + warp * 32 + qi;

        // q -> 8 packed ull (uniform across warp, L1-hot)
        const float4* Qp = (const float4*)(Qb + (size_t)g * 16);
        F4U q0, q1, q2, q3;
        q0.f = Qp[0]; q1.f = Qp[1]; q2.f = Qp[2]; q3.f = Qp[3];

        // mask row (coalesced: p = lane + 32i)
        const float* mrow = mask + (size_t)(b * Gg + g) * Pp;
        float mk[16];
#pragma unroll
        for (int i = 0; i < 16; i++) mk[i] = mrow[lane + 32 * i];

        // scores for this lane's 16 keys
        float s[16];
#pragma unroll
        for (int i = 0; i < 16; i++) {
            const float* kr = &sK[(lane + 32 * i) * AT_STR];
            F4U ka, kb2, kc2, kd;
            ka.f = *(const float4*)kr;
            kb2.f = *(const float4*)(kr + 4);
            kc2.f = *(const float4*)(kr + 8);
            kd.f = *(const float4*)(kr + 12);
            ull acc = 0ull;
            fma2(acc, q0.u[0], ka.u[0]);  fma2(acc, q0.u[1], ka.u[1]);
            fma2(acc, q1.u[0], kb2.u[0]); fma2(acc, q1.u[1], kb2.u[1]);
            fma2(acc, q2.u[0], kc2.u[0]); fma2(acc, q2.u[1], kc2.u[1]);
            fma2(acc, q3.u[0], kd.u[0]);  fma2(acc, q3.u[1], kd.u[1]);
            float2 f = unpack2(acc);
            s[i] = (f.x + f.y) * 0.25f + mk[i];
        }

        // warp softmax
        float mx = s[0];
#pragma unroll
        for (int i = 1; i < 16; i++) mx = fmaxf(mx, s[i]);
#pragma unroll
        for (int o = 16; o > 0; o >>= 1)
            mx = fmaxf(mx, __shfl_xor_sync(0xffffffffu, mx, o));
        float sum = 0.f;
#pragma unroll
        for (int i = 0; i < 16; i++) {
            s[i] = __expf(s[i] - mx);
            sum += s[i];
        }
#pragma unroll
        for (int o = 16; o > 0; o >>= 1)
            sum += __shfl_xor_sync(0xffffffffu, sum, o);
        const float inv = __fdividef(1.f, sum);

        // AV: acc8[j] = packed kc pair (2j, 2j+1)
        ull acc8[8];
#pragma unroll
        for (int j = 0; j < 8; j++) acc8[j] = 0ull;
#pragma unroll
        for (int i = 0; i < 16; i++) {
            const float* vr = &sV[(lane + 32 * i) * AT_STR];
            F4U va, vb2, vc2, vd;
            va.f = *(const float4*)vr;
            vb2.f = *(const float4*)(vr + 4);
            vc2.f = *(const float4*)(vr + 8);
            vd.f = *(const float4*)(vr + 12);
            ull wd = dup2(s[i]);
            fma2(acc8[0], wd, va.u[0]);  fma2(acc8[1], wd, va.u[1]);
            fma2(acc8[2], wd, vb2.u[0]); fma2(acc8[3], wd, vb2.u[1]);
            fma2(acc8[4], wd, vc2.u[0]); fma2(acc8[5], wd, vc2.u[1]);
            fma2(acc8[6], wd, vd.u[0]);  fma2(acc8[7], wd, vd.u[1]);
        }
        const ull ivd = dup2(inv);
#pragma unroll
        for (int j = 0; j < 8; j++) acc8[j] = mul2(acc8[j], ivd);

        // reduce-scatter butterfly over lanes
        // r1 (xor16): 8 -> 4 ull; keep-half selects kc bit3
        ull n4[4];
#pragma unroll
        for (int j = 0; j < 4; j++) {
            ull snd = (lane & 16) ? acc8[j] : acc8[j + 4];
            ull kp  = (lane & 16) ? acc8[j + 4] : acc8[j];
            n4[j] = add2(kp, __shfl_xor_sync(0xffffffffu, snd, 16));
        }
        // r2 (xor8): 4 -> 2; kc bit2
        ull n2[2];
#pragma unroll
        for (int j = 0; j < 2; j++) {
            ull snd = (lane & 8) ? n4[j] : n4[j + 2];
            ull kp  = (lane & 8) ? n4[j + 2] : n4[j];
            n2[j] = add2(kp, __shfl_xor_sync(0xffffffffu, snd, 8));
        }
        // r3 (xor4): 2 -> 1; kc bit1
        ull n1;
        {
            ull snd = (lane & 4) ? n2[0] : n2[1];
            ull kp  = (lane & 4) ? n2[1] : n2[0];
            n1 = add2(kp, __shfl_xor_sync(0xffffffffu, snd, 4));
        }
        // r4 (xor2): split ull; kc bit0
        float2 t = unpack2(n1);
        float fs = (lane & 2) ? t.x : t.y;
        float fk = (lane & 2) ? t.y : t.x;
        float f = fk + __shfl_xor_sync(0xffffffffu, fs, 2);
        // r5 (xor1): final reduce (pairs hold identical result)
        f += __shfl_xor_sync(0xffffffffu, f, 1);

        if (!(lane & 1))
            g_attn[(size_t)(b * Gg + g) * HK + h * 16 + kcout] = f;
    }
}

// ---------------------------------------------------------------------------
__global__ __launch_bounds__(256)
void softmax_kernel(float* __restrict__ out) {
    __shared__ float sred[8];
    __shared__ float sbc[2];
    const int row = blockIdx.x;
    const int tid = threadIdx.x;
    const float* in = g_s2 + (size_t)row * Pp;

    float v0 = in[tid], v1 = in[tid + 256];
    float lmax = fmaxf(v0, v1);
#pragma unroll
    for (int o = 16; o > 0; o >>= 1)
        lmax = fmaxf(lmax, __shfl_xor_sync(0xffffffffu, lmax, o));
    if ((tid & 31) == 0) sred[tid >> 5] = lmax;
    __syncthreads();
    if (tid == 0) {
        float m = sred[0];
#pragma unroll
        for (int w = 1; w < 8; w++) m = fmaxf(m, sred[w]);
        sbc[0] = m;
    }
    __syncthreads();
    float smax = sbc[0];

    float e0 = __expf(v0 - smax), e1 = __expf(v1 - smax);
    float lsum = e0 + e1;
#pragma unroll
    for (int o = 16; o > 0; o >>= 1)
        lsum += __shfl_xor_sync(0xffffffffu, lsum, o);
    if ((tid & 31) == 0) sred[tid >> 5] = lsum;
    __syncthreads();
    if (tid == 0) {
        float s = 0.f;
#pragma unroll
        for (int w = 0; w < 8; w++) s += sred[w];
        sbc[1] = 1.f / s;
    }
    __syncthreads();
    float inv = sbc[1];
    out[(size_t)row * Pp + tid] = e0 * inv;
    out[(size_t)row * Pp + tid + 256] = e1 * inv;
}

// ---------------------------------------------------------------------------
extern "C" void kernel_launch(void* const* d_in, const int* in_sizes, int n_in,
                              void* d_out, int out_size) {
    const float* input1 = (const float*)d_in[0];
    const float* input2 = (const float*)d_in[1];
    const float* ctime  = (const float*)d_in[2];
    const float* mask   = (const float*)d_in[3];
    const float* enc    = (const float*)d_in[4];
    const float* Wq     = (const float*)d_in[5];
    const float* Wk     = (const float*)d_in[6];
    const float* Wv     = (const float*)d_in[7];
    const float* Wcw    = (const float*)d_in[8];
    const float* Wcb    = (const float*)d_in[9];
    float* out = (float*)d_out;

    qbias_kernel<<<Bb, 256>>>(input1, Wq);

    proj_kernel<<<dim3(64, 2, 3), 256>>>(enc, input2, Wk, Wv,
                                         Wq + Ee * HK, ctime, Wq + 2 * Ee * HK);

    cudaFuncSetAttribute(attn_kernel, cudaFuncAttributeMaxDynamicSharedMemorySize,
                         ATTN_SMEM_BYTES);
    attn_kernel<<<dim3(2, Hh, Bb), 256, ATTN_SMEM_BYTES>>>(mask);

    wc_kernel<<<dim3(64, 2), 256>>>(Wcw, Wcb);

    pointer_gemm<<<dim3(4, 4, Bb), 256>>>(enc, mask);

    softmax_kernel<<<Bb * Gg, 256>>>(out);
}

// round 6
// speedup vs baseline: 1.7139x; 1.4458x over previous
#include <cuda_runtime.h>
#include <math.h>

#define Bb 16
#define Gg 512
#define Pp 512
#define Ee 256
#define Hh 16
#define Kd 16
#define HK 256

typedef unsigned long long ull;

// Scratch (device globals: allocation-free rule)
__device__ float g_c1[Bb * HK];
__device__ float g_Kt[Bb * Hh * Pp * Kd];   // [B,H,P,Kd]
__device__ float g_Vt[Bb * Hh * Pp * Kd];
__device__ float g_Qt[Bb * Hh * Gg * Kd];
__device__ float g_attn[Bb * Gg * HK];
__device__ float g_mh[Bb * Gg * HK];
__device__ float g_s2[Bb * Gg * Pp];

// ---- packed f32x2 helpers ---------------------------------------------------
__device__ __forceinline__ ull dup2(float a) {
    ull r; asm("mov.b64 %0, {%1, %1};" : "=l"(r) : "f"(a)); return r;
}
__device__ __forceinline__ void fma2(ull& d, ull a, ull b) {
    asm("fma.rn.f32x2 %0, %1, %2, %3;" : "=l"(d) : "l"(a), "l"(b), "l"(d));
}
__device__ __forceinline__ float2 unpack2(ull v) {
    float2 f; asm("mov.b64 {%0, %1}, %2;" : "=f"(f.x), "=f"(f.y) : "l"(v)); return f;
}
__device__ __forceinline__ ull add2(ull a, ull b) {
    ull r; asm("add.rn.f32x2 %0, %1, %2;" : "=l"(r) : "l"(a), "l"(b)); return r;
}
__device__ __forceinline__ ull mul2(ull a, ull b) {
    ull r; asm("mul.rn.f32x2 %0, %1, %2;" : "=l"(r) : "l"(a), "l"(b)); return r;
}

union F4U { float4 f; ull u[2]; };

// ---------------------------------------------------------------------------
__global__ void qbias_kernel(const float* __restrict__ input1,
                             const float* __restrict__ Wq) {
    int b = blockIdx.x;
    int n = threadIdx.x;
    const float* x = input1 + b * Ee;
    float acc = 0.f;
#pragma unroll 4
    for (int e = 0; e < Ee; e++) acc += x[e] * Wq[e * HK + n];
    g_c1[b * HK + n] = acc;
}

// ---------------------------------------------------------------------------
// 128x128 tile GEMM (256 threads, 8x8 micro-tile via 8x4 packed f32x2, BK=8)
// ---------------------------------------------------------------------------
#define GEMM_PROLOG()                                                     \
    __shared__ float As[8][132];                                          \
    __shared__ float Bs[8][132];                                          \
    const int tid = threadIdx.x;                                          \
    const int warp = tid >> 5, lane = tid & 31;                           \
    const int tm = ((warp >> 2) << 3) + (lane >> 2);                      \
    const int tn = ((warp & 3) << 2) + (lane & 3);                        \
    const int ar = tid >> 1, ac = (tid & 1) * 4;                          \
    const int br = tid >> 5, bc = (tid & 31) * 4;                         \
    ull acc2[8][4];                                                       \
    _Pragma("unroll") for (int i = 0; i < 8; i++)                         \
    _Pragma("unroll") for (int j = 0; j < 4; j++) acc2[i][j] = 0ull;

#define GEMM_INNER2()                                                     \
    _Pragma("unroll")                                                     \
    for (int kk = 0; kk < 8; kk++) {                                      \
        float4 a0 = *(const float4*)&As[kk][tm * 8];                      \
        float4 a1 = *(const float4*)&As[kk][tm * 8 + 4];                  \
        const ull* bp = (const ull*)&Bs[kk][tn * 8];                      \
        ull b0 = bp[0], b1 = bp[1], b2 = bp[2], b3 = bp[3];               \
        float aa[8] = {a0.x, a0.y, a0.z, a0.w, a1.x, a1.y, a1.z, a1.w};   \
        _Pragma("unroll") for (int i = 0; i < 8; i++) {                   \
            ull ad = dup2(aa[i]);                                         \
            fma2(acc2[i][0], ad, b0);                                     \
            fma2(acc2[i][1], ad, b1);                                     \
            fma2(acc2[i][2], ad, b2);                                     \
            fma2(acc2[i][3], ad, b3);                                     \
        }                                                                 \
    }

#define GEMM_LOOP_NN(Aptr, Wptr, m0, n0)                                  \
    {                                                                     \
        const float* Ag = (Aptr) + (size_t)((m0) + ar) * 256 + ac;        \
        const float* Bg = (Wptr) + (size_t)br * 256 + (n0) + bc;          \
        float4 av = *(const float4*)Ag;                                   \
        float4 bv = *(const float4*)Bg;                                   \
        for (int k0 = 0; k0 < 256; k0 += 8) {                             \
            As[ac + 0][ar] = av.x; As[ac + 1][ar] = av.y;                 \
            As[ac + 2][ar] = av.z; As[ac + 3][ar] = av.w;                 \
            *(float4*)&Bs[br][bc] = bv;                                   \
            __syncthreads();                                              \
            if (k0 < 248) {                                               \
                av = *(const float4*)(Ag + k0 + 8);                       \
                bv = *(const float4*)(Bg + (size_t)(k0 + 8) * 256);       \
            }                                                             \
            GEMM_INNER2();                                                \
            __syncthreads();                                              \
        }                                                                 \
    }

#define GEMM_LOOP_NT(Aptr, Bptr, m0, n0)                                  \
    {                                                                     \
        const float* Ag = (Aptr) + (size_t)((m0) + ar) * 256 + ac;        \
        const float* Bg2 = (Bptr) + (size_t)((n0) + ar) * 256 + ac;       \
        float4 av = *(const float4*)Ag;                                   \
        float4 bv = *(const float4*)Bg2;                                  \
        for (int k0 = 0; k0 < 256; k0 += 8) {                             \
            As[ac + 0][ar] = av.x; As[ac + 1][ar] = av.y;                 \
            As[ac + 2][ar] = av.z; As[ac + 3][ar] = av.w;                 \
            Bs[ac + 0][ar] = bv.x; Bs[ac + 1][ar] = bv.y;                 \
            Bs[ac + 2][ar] = bv.z; Bs[ac + 3][ar] = bv.w;                 \
            __syncthreads();                                              \
            if (k0 < 248) {                                               \
                av = *(const float4*)(Ag + k0 + 8);                       \
                bv = *(const float4*)(Bg2 + k0 + 8);                      \
            }                                                             \
            GEMM_INNER2();                                                \
            __syncthreads();                                              \
        }                                                                 \
    }

// ---------------------------------------------------------------------------
// Fused projections: z=0 K, z=1 V, z=2 Q (+c1 + t*wq_last). Heads layout out.
// ---------------------------------------------------------------------------
__global__ __launch_bounds__(256, 2)
void proj_kernel(const float* __restrict__ enc, const float* __restrict__ inp2,
                 const float* __restrict__ Wk, const float* __restrict__ Wv,
                 const float* __restrict__ Wqm, const float* __restrict__ tvec,
                 const float* __restrict__ wql) {
    const int z = blockIdx.z;
    const float* A = (z == 2) ? inp2 : enc;
    const float* W = (z == 0) ? Wk : (z == 1) ? Wv : Wqm;
    float* C = (z == 0) ? g_Kt : (z == 1) ? g_Vt : g_Qt;
    const int m0 = blockIdx.x * 128, n0 = blockIdx.y * 128;

    GEMM_PROLOG();
    GEMM_LOOP_NN(A, W, m0, n0);

#pragma unroll
    for (int i = 0; i < 8; i++) {
        int m = m0 + tm * 8 + i;
        int bb = m >> 9, r = m & 511;
        int nb = n0 + tn * 8;
        float v[8];
#pragma unroll
        for (int j = 0; j < 4; j++) {
            float2 f = unpack2(acc2[i][j]);
            v[2 * j] = f.x; v[2 * j + 1] = f.y;
        }
        if (z == 2) {
            float t = tvec[m];
#pragma unroll
            for (int j = 0; j < 8; j++) {
                int n = nb + j;
                v[j] += g_c1[bb * HK + n] + t * wql[n];
            }
        }
        int h = nb >> 4, kcb = nb & 15;
        float* dst = C + (((size_t)(bb * Hh + h) * 512 + r) << 4) + kcb;
        *(float4*)dst = make_float4(v[0], v[1], v[2], v[3]);
        *(float4*)(dst + 4) = make_float4(v[4], v[5], v[6], v[7]);
    }
}

// ---------------------------------------------------------------------------
__global__ __launch_bounds__(256, 2)
void wc_kernel(const float* __restrict__ Wcw, const float* __restrict__ bias) {
    const int m0 = blockIdx.x * 128, n0 = blockIdx.y * 128;
    GEMM_PROLOG();
    GEMM_LOOP_NN(g_attn, Wcw, m0, n0);

#pragma unroll
    for (int i = 0; i < 8; i++) {
        int m = m0 + tm * 8 + i;
        int nb = n0 + tn * 8;
        float v[8];
#pragma unroll
        for (int j = 0; j < 4; j++) {
            float2 f = unpack2(acc2[i][j]);
            v[2 * j] = f.x + bias[nb + 2 * j];
            v[2 * j + 1] = f.y + bias[nb + 2 * j + 1];
        }
        float* dst = g_mh + (size_t)m * 256 + nb;
        *(float4*)dst = make_float4(v[0], v[1], v[2], v[3]);
        *(float4*)(dst + 4) = make_float4(v[4], v[5], v[6], v[7]);
    }
}

// ---------------------------------------------------------------------------
__device__ __forceinline__ float fast_tanh10(float x) {
    x = fminf(fmaxf(x, -15.f), 15.f);
    float e = __expf(2.f * x);
    return 10.f * (1.f - __fdividef(2.f, e + 1.f));
}

__global__ __launch_bounds__(256, 2)
void pointer_gemm(const float* __restrict__ enc, const float* __restrict__ mask) {
    const int b = blockIdx.z;
    const int g0 = blockIdx.x * 128, p0 = blockIdx.y * 128;
    const float* A = g_mh + (size_t)b * Gg * HK;
    const float* Bm = enc + (size_t)b * Pp * Ee;

    GEMM_PROLOG();
    GEMM_LOOP_NT(A, Bm, g0, p0);

#pragma unroll
    for (int i = 0; i < 8; i++) {
        int g = g0 + tm * 8 + i;
        size_t base = (size_t)(b * Gg + g) * Pp + p0 + tn * 8;
        float v[8];
#pragma unroll
        for (int j = 0; j < 4; j++) {
            float2 f = unpack2(acc2[i][j]);
            v[2 * j] = fast_tanh10(f.x * 0.0625f) + mask[base + 2 * j];
            v[2 * j + 1] = fast_tanh10(f.y * 0.0625f) + mask[base + 2 * j + 1];
        }
        *(float4*)&g_s2[base] = make_float4(v[0], v[1], v[2], v[3]);
        *(float4*)&g_s2[base + 4] = make_float4(v[4], v[5], v[6], v[7]);
    }
}

// ---------------------------------------------------------------------------
// Warp-autonomous attention, 4 queries per pass (K/V smem reads amortized 4x).
// Block = (g-half, h, b), 8 warps, 32 q per warp = 8 passes.
// One block barrier total. Crossbar traffic: 4 MB/block (was 16 MB).
// ---------------------------------------------------------------------------
#define AT_STR 20
#define ATTN_SMEM_BYTES (2 * 512 * AT_STR * 4)   // 81920 B

__global__ __launch_bounds__(256, 1)
void attn_kernel(const float* __restrict__ mask) {
    extern __shared__ float sm[];
    float* sK = sm;                   // [512][20]
    float* sV = sm + 512 * AT_STR;    // [512][20]

    const int tid = threadIdx.x;
    const int gbase = blockIdx.x * 256;
    const int h = blockIdx.y, b = blockIdx.z;
    const float* Kb = g_Kt + (size_t)(b * Hh + h) * Pp * Kd;
    const float* Vb = g_Vt + (size_t)(b * Hh + h) * Pp * Kd;
    const float* Qb = g_Qt + (size_t)(b * Hh + h) * Gg * Kd;

    for (int i = tid; i < 2048; i += 256) {
        int p = i >> 2, c = (i & 3) * 4;
        *(float4*)&sK[p * AT_STR + c] = ((const float4*)Kb)[i];
        *(float4*)&sV[p * AT_STR + c] = ((const float4*)Vb)[i];
    }
    __syncthreads();   // the ONLY block barrier

    const int warp = tid >> 5, lane = tid & 31;
    const int kcout = (((lane >> 4) & 1) << 3) | (((lane >> 3) & 1) << 2) |
                      (((lane >> 2) & 1) << 1) | ((lane >> 1) & 1);

    for (int pass = 0; pass < 8; pass++) {
        const int g0 = gbase + warp * 32 + pass * 4;

        // 4 query vectors (uniform across warp)
        F4U q[4][4];
#pragma unroll
        for (int qq = 0; qq < 4; qq++) {
            const float4* Qp = (const float4*)(Qb + (size_t)(g0 + qq) * 16);
            q[qq][0].f = Qp[0]; q[qq][1].f = Qp[1];
            q[qq][2].f = Qp[2]; q[qq][3].f = Qp[3];
        }

        // scores: each K row read once serves 4 queries
        float s[4][16];
#pragma unroll
        for (int i = 0; i < 16; i++) {
            const float* kr = &sK[(lane + 32 * i) * AT_STR];
            F4U k0, k1, k2, k3;
            k0.f = *(const float4*)kr;
            k1.f = *(const float4*)(kr + 4);
            k2.f = *(const float4*)(kr + 8);
            k3.f = *(const float4*)(kr + 12);
#pragma unroll
            for (int qq = 0; qq < 4; qq++) {
                ull a = 0ull;
                fma2(a, q[qq][0].u[0], k0.u[0]); fma2(a, q[qq][0].u[1], k0.u[1]);
                fma2(a, q[qq][1].u[0], k1.u[0]); fma2(a, q[qq][1].u[1], k1.u[1]);
                fma2(a, q[qq][2].u[0], k2.u[0]); fma2(a, q[qq][2].u[1], k2.u[1]);
                fma2(a, q[qq][3].u[0], k3.u[0]); fma2(a, q[qq][3].u[1], k3.u[1]);
                float2 f = unpack2(a);
                s[qq][i] = f.x + f.y;
            }
        }

        // mask + scale, then warp softmax per query
        float inv[4];
#pragma unroll
        for (int qq = 0; qq < 4; qq++) {
            const float* mrow = mask + (size_t)(b * Gg + g0 + qq) * Pp + lane;
            float mk[16];
#pragma unroll
            for (int i = 0; i < 16; i++) mk[i] = mrow[32 * i];
#pragma unroll
            for (int i = 0; i < 16; i++) s[qq][i] = s[qq][i] * 0.25f + mk[i];

            float mx = s[qq][0];
#pragma unroll
            for (int i = 1; i < 16; i++) mx = fmaxf(mx, s[qq][i]);
#pragma unroll
            for (int o = 16; o > 0; o >>= 1)
                mx = fmaxf(mx, __shfl_xor_sync(0xffffffffu, mx, o));
            float sum = 0.f;
#pragma unroll
            for (int i = 0; i < 16; i++) {
                s[qq][i] = __expf(s[qq][i] - mx);
                sum += s[qq][i];
            }
#pragma unroll
            for (int o = 16; o > 0; o >>= 1)
                sum += __shfl_xor_sync(0xffffffffu, sum, o);
            inv[qq] = __fdividef(1.f, sum);
        }

        // AV: each V row read once serves 4 queries
        ull acc[4][8];
#pragma unroll
        for (int qq = 0; qq < 4; qq++)
#pragma unroll
            for (int j = 0; j < 8; j++) acc[qq][j] = 0ull;

#pragma unroll
        for (int i = 0; i < 16; i++) {
            const float* vr = &sV[(lane + 32 * i) * AT_STR];
            F4U v0, v1, v2, v3;
            v0.f = *(const float4*)vr;
            v1.f = *(const float4*)(vr + 4);
            v2.f = *(const float4*)(vr + 8);
            v3.f = *(const float4*)(vr + 12);
#pragma unroll
            for (int qq = 0; qq < 4; qq++) {
                ull wd = dup2(s[qq][i]);
                fma2(acc[qq][0], wd, v0.u[0]); fma2(acc[qq][1], wd, v0.u[1]);
                fma2(acc[qq][2], wd, v1.u[0]); fma2(acc[qq][3], wd, v1.u[1]);
                fma2(acc[qq][4], wd, v2.u[0]); fma2(acc[qq][5], wd, v2.u[1]);
                fma2(acc[qq][6], wd, v3.u[0]); fma2(acc[qq][7], wd, v3.u[1]);
            }
        }

        // per-query: scale, butterfly reduce-scatter, write
#pragma unroll
        for (int qq = 0; qq < 4; qq++) {
            const ull ivd = dup2(inv[qq]);
            ull a8[8];
#pragma unroll
            for (int j = 0; j < 8; j++) a8[j] = mul2(acc[qq][j], ivd);

            ull n4[4];
#pragma unroll
            for (int j = 0; j < 4; j++) {
                ull snd = (lane & 16) ? a8[j] : a8[j + 4];
                ull kp  = (lane & 16) ? a8[j + 4] : a8[j];
                n4[j] = add2(kp, __shfl_xor_sync(0xffffffffu, snd, 16));
            }
            ull n2[2];
#pragma unroll
            for (int j = 0; j < 2; j++) {
                ull snd = (lane & 8) ? n4[j] : n4[j + 2];
                ull kp  = (lane & 8) ? n4[j + 2] : n4[j];
                n2[j] = add2(kp, __shfl_xor_sync(0xffffffffu, snd, 8));
            }
            ull n1;
            {
                ull snd = (lane & 4) ? n2[0] : n2[1];
                ull kp  = (lane & 4) ? n2[1] : n2[0];
                n1 = add2(kp, __shfl_xor_sync(0xffffffffu, snd, 4));
            }
            float2 t = unpack2(n1);
            float fs = (lane & 2) ? t.x : t.y;
            float fk = (lane & 2) ? t.y : t.x;
            float f = fk + __shfl_xor_sync(0xffffffffu, fs, 2);
            f += __shfl_xor_sync(0xffffffffu, f, 1);

            if (!(lane & 1))
                g_attn[(size_t)(b * Gg + g0 + qq) * HK + h * 16 + kcout] = f;
        }
    }
}

// ---------------------------------------------------------------------------
__global__ __launch_bounds__(256)
void softmax_kernel(float* __restrict__ out) {
    __shared__ float sred[8];
    __shared__ float sbc[2];
    const int row = blockIdx.x;
    const int tid = threadIdx.x;
    const float* in = g_s2 + (size_t)row * Pp;

    float v0 = in[tid], v1 = in[tid + 256];
    float lmax = fmaxf(v0, v1);
#pragma unroll
    for (int o = 16; o > 0; o >>= 1)
        lmax = fmaxf(lmax, __shfl_xor_sync(0xffffffffu, lmax, o));
    if ((tid & 31) == 0) sred[tid >> 5] = lmax;
    __syncthreads();
    if (tid == 0) {
        float m = sred[0];
#pragma unroll
        for (int w = 1; w < 8; w++) m = fmaxf(m, sred[w]);
        sbc[0] = m;
    }
    __syncthreads();
    float smax = sbc[0];

    float e0 = __expf(v0 - smax), e1 = __expf(v1 - smax);
    float lsum = e0 + e1;
#pragma unroll
    for (int o = 16; o > 0; o >>= 1)
        lsum += __shfl_xor_sync(0xffffffffu, lsum, o);
    if ((tid & 31) == 0) sred[tid >> 5] = lsum;
    __syncthreads();
    if (tid == 0) {
        float s = 0.f;
#pragma unroll
        for (int w = 0; w < 8; w++) s += sred[w];
        sbc[1] = 1.f / s;
    }
    __syncthreads();
    float inv = sbc[1];
    out[(size_t)row * Pp + tid] = e0 * inv;
    out[(size_t)row * Pp + tid + 256] = e1 * inv;
}

// ---------------------------------------------------------------------------
extern "C" void kernel_launch(void* const* d_in, const int* in_sizes, int n_in,
                              void* d_out, int out_size) {
    const float* input1 = (const float*)d_in[0];
    const float* input2 = (const float*)d_in[1];
    const float* ctime  = (const float*)d_in[2];
    const float* mask   = (const float*)d_in[3];
    const float* enc    = (const float*)d_in[4];
    const float* Wq     = (const float*)d_in[5];
    const float* Wk     = (const float*)d_in[6];
    const float* Wv     = (const float*)d_in[7];
    const float* Wcw    = (const float*)d_in[8];
    const float* Wcb    = (const float*)d_in[9];
    float* out = (float*)d_out;

    qbias_kernel<<<Bb, 256>>>(input1, Wq);

    proj_kernel<<<dim3(64, 2, 3), 256>>>(enc, input2, Wk, Wv,
                                         Wq + Ee * HK, ctime, Wq + 2 * Ee * HK);

    cudaFuncSetAttribute(attn_kernel, cudaFuncAttributeMaxDynamicSharedMemorySize,
                         ATTN_SMEM_BYTES);
    attn_kernel<<<dim3(2, Hh, Bb), 256, ATTN_SMEM_BYTES>>>(mask);

    wc_kernel<<<dim3(64, 2), 256>>>(Wcw, Wcb);

    pointer_gemm<<<dim3(4, 4, Bb), 256>>>(enc, mask);

    softmax_kernel<<<Bb * Gg, 256>>>(out);
}